// round 4
// baseline (speedup 1.0000x reference)
#include <cuda_runtime.h>
#include <cstdint>

#define BB 32
#define SS 512
#define DD 768
#define OO 768
#define EE 8
#define SCH 16                     // pool s-chunks

#define BM 128
#define BN 128
#define BK 32
#define KCH (DD / BK)              // 24 k-chunks
#define LDA 36                     // padded row stride (floats)
#define BUFSZ (128 * LDA)          // floats per tile buffer

// ---------------- scratch (device globals; no allocation allowed) ----------
__device__ float g_pool_part[SCH * BB * DD];
__device__ float g_gate_val[BB * 2];
__device__ int   g_gate_idx[BB * 2];
__device__ float g_wc[(size_t)BB * OO * DD];   // 75.5MB combined expert weights
__device__ float g_bias_c[BB * OO];

// ---------------- kernel 1: partial pooled sums ------------------------------
__global__ void smoe_pool_kernel(const float* __restrict__ x) {
    const int b = blockIdx.x;
    const int sc = blockIdx.y;
    const int d = blockIdx.z * 256 + threadIdx.x;
    const float* xp = x + (size_t)b * SS * DD + (size_t)sc * (SS / SCH) * DD + d;
    float sum = 0.f;
#pragma unroll
    for (int i = 0; i < SS / SCH; i++) sum += xp[(size_t)i * DD];
    g_pool_part[(sc * BB + b) * DD + d] = sum;
}

// ---------------- kernel 2: gating + top-2 + aux loss ------------------------
__device__ __forceinline__ float cv_squared8(const float* v) {
    float m = 0.f;
#pragma unroll
    for (int e = 0; e < EE; e++) m += v[e];
    m *= (1.0f / EE);
    float var = 0.f;
#pragma unroll
    for (int e = 0; e < EE; e++) { float dv = v[e] - m; var += dv * dv; }
    var *= (1.0f / (EE - 1));
    return var / (m * m + 1e-10f);
}

__global__ void smoe_gate_kernel(const float* __restrict__ w_gate,
                                 float* __restrict__ loss_out) {
    const int b = threadIdx.x;
    __shared__ float sh_gates[BB][EE];

    float logits[EE];
#pragma unroll
    for (int e = 0; e < EE; e++) logits[e] = 0.f;

    for (int d = 0; d < DD; d++) {
        float pv = 0.f;
#pragma unroll
        for (int s = 0; s < SCH; s++) pv += g_pool_part[(s * BB + b) * DD + d];
        pv *= (1.0f / SS);
#pragma unroll
        for (int e = 0; e < EE; e++) logits[e] += pv * w_gate[d * EE + e];
    }

    int i1 = 0; float v1 = logits[0];
#pragma unroll
    for (int e = 1; e < EE; e++) if (logits[e] > v1) { v1 = logits[e]; i1 = e; }
    int i2 = -1; float v2 = -1e30f;
#pragma unroll
    for (int e = 0; e < EE; e++)
        if (e != i1 && logits[e] > v2) { v2 = logits[e]; i2 = e; }

    float ex = expf(v2 - v1);
    float inv = 1.0f / (1.0f + ex);
    float gtop = inv, gsec = ex * inv;

#pragma unroll
    for (int e = 0; e < EE; e++) sh_gates[b][e] = 0.f;
    sh_gates[b][i1] = gtop;
    sh_gates[b][i2] = gsec;

    g_gate_idx[b * 2 + 0] = i1;
    g_gate_idx[b * 2 + 1] = i2;
    g_gate_val[b * 2 + 0] = gtop;
    g_gate_val[b * 2 + 1] = gsec;

    __syncthreads();

    if (b == 0) {
        float imp[EE], ldv[EE];
#pragma unroll
        for (int e = 0; e < EE; e++) {
            float s = 0.f, c = 0.f;
            for (int bi = 0; bi < BB; bi++) {
                float g = sh_gates[bi][e];
                s += g;
                if (g > 0.f) c += 1.f;
            }
            imp[e] = s; ldv[e] = c;
        }
        loss_out[0] = (cv_squared8(imp) + cv_squared8(ldv)) * 0.01f;
    }
}

// ---------------- kernel 2.5: combine expert weights/bias per batch ----------
__global__ void smoe_combine_kernel(const float* __restrict__ weight,
                                    const float* __restrict__ bias) {
    const int b = blockIdx.y;
    const int e0 = g_gate_idx[2 * b], e1 = g_gate_idx[2 * b + 1];
    const float g0 = g_gate_val[2 * b], g1 = g_gate_val[2 * b + 1];

    const int i = blockIdx.x * 256 + threadIdx.x;   // float4 index
    const float4* w0 = (const float4*)(weight + (size_t)e0 * OO * DD);
    const float4* w1 = (const float4*)(weight + (size_t)e1 * OO * DD);
    float4* wc = (float4*)(g_wc + (size_t)b * OO * DD);
    float4 a = w0[i], c = w1[i], r;
    r.x = g0 * a.x + g1 * c.x; r.y = g0 * a.y + g1 * c.y;
    r.z = g0 * a.z + g1 * c.z; r.w = g0 * a.w + g1 * c.w;
    wc[i] = r;

    if (blockIdx.x == 0 && threadIdx.x < OO / 4) {
        const float4* b0 = (const float4*)(bias + (size_t)e0 * OO);
        const float4* b1 = (const float4*)(bias + (size_t)e1 * OO);
        float4 x0 = b0[threadIdx.x], x1 = b1[threadIdx.x], rb;
        rb.x = g0 * x0.x + g1 * x1.x; rb.y = g0 * x0.y + g1 * x1.y;
        rb.z = g0 * x0.z + g1 * x1.z; rb.w = g0 * x0.w + g1 * x1.w;
        ((float4*)(g_bias_c + b * OO))[threadIdx.x] = rb;
    }
}

// ---------------- kernel 3: TF32 mma.sync GEMM (2-operand) -------------------
__device__ __forceinline__ uint32_t smem_u32(const void* p) {
    return (uint32_t)__cvta_generic_to_shared(p);
}

__device__ __forceinline__ void ldsm_x4(uint32_t (&r)[4], uint32_t addr) {
    asm volatile("ldmatrix.sync.aligned.m8n8.x4.shared.b16 {%0,%1,%2,%3}, [%4];"
                 : "=r"(r[0]), "=r"(r[1]), "=r"(r[2]), "=r"(r[3]) : "r"(addr));
}

__device__ __forceinline__ void mma_tf32(float (&d)[4], const uint32_t (&a)[4],
                                         uint32_t b0, uint32_t b1) {
    asm volatile(
        "mma.sync.aligned.m16n8k8.row.col.f32.tf32.tf32.f32 "
        "{%0,%1,%2,%3}, {%4,%5,%6,%7}, {%8,%9}, {%0,%1,%2,%3};"
        : "+f"(d[0]), "+f"(d[1]), "+f"(d[2]), "+f"(d[3])
        : "r"(a[0]), "r"(a[1]), "r"(a[2]), "r"(a[3]), "r"(b0), "r"(b1));
}

__device__ __forceinline__ void cp_async16(uint32_t dst, const float* src) {
    asm volatile("cp.async.ca.shared.global [%0], [%1], 16;" :: "r"(dst), "l"(src));
}

__global__ __launch_bounds__(256, 2)
void smoe_gemm_tf32(const float* __restrict__ x,
                    float* __restrict__ out) {
    extern __shared__ float sm[];
    float* As = sm;                  // [2][BUFSZ]
    float* Bs = sm + 2 * BUFSZ;      // [2][BUFSZ]

    const int b = blockIdx.z;
    const int nBlk = blockIdx.x * BN;
    const int mBlk = blockIdx.y * BM;

    const int tid = threadIdx.x;
    const int lane = tid & 31;
    const int wid = tid >> 5;
    const int warpM = wid >> 2;      // 0..1 -> 64-row slab
    const int warpN = wid & 3;       // 0..3 -> 32-col slab

    const float* gA = x    + (size_t)b * SS * DD + (size_t)mBlk * DD;
    const float* gB = g_wc + (size_t)b * OO * DD + (size_t)nBlk * DD;

    // A frag (16x8): row = lane%8 + 8*(lane/8 %2), k-half = lane/16
    const int aRow = (lane & 7) + ((lane >> 3) & 1) * 8;
    const int aK   = ((lane >> 4) & 1) * 4;
    int aOff[4];
#pragma unroll
    for (int mf = 0; mf < 4; mf++)
        aOff[mf] = (warpM * 64 + mf * 16 + aRow) * LDA + aK;

    // B pair (16 n-rows): row = lane%8 + 8*(lane/16), k-half = lane/8 %2
    const int bRow = (lane & 7) + ((lane >> 4) & 1) * 8;
    const int bK   = ((lane >> 3) & 1) * 4;
    int bOff[2];
#pragma unroll
    for (int p = 0; p < 2; p++)
        bOff[p] = (warpN * 32 + p * 16 + bRow) * LDA + bK;

    float acc[4][4][4];
#pragma unroll
    for (int i = 0; i < 4; i++)
#pragma unroll
        for (int j = 0; j < 4; j++)
#pragma unroll
            for (int k = 0; k < 4; k++) acc[i][j][k] = 0.f;

    // --- cp.async tile loader: 128x32 floats per stream ---------------------
    auto issue = [&](int chunk, int buf) {
        const int kt = chunk * BK;
#pragma unroll
        for (int p = 0; p < 4; p++) {
            int c = tid + p * 256;
            int m = c >> 3;
            int k4 = (c & 7) * 4;
            int so = buf * BUFSZ + m * LDA + k4;
            size_t go = (size_t)m * DD + kt + k4;
            cp_async16(smem_u32(As + so), gA + go);
            cp_async16(smem_u32(Bs + so), gB + go);
        }
        asm volatile("cp.async.commit_group;");
    };

    issue(0, 0);

#pragma unroll 1
    for (int c = 0; c < KCH; c++) {
        const int buf = c & 1;
        if (c + 1 < KCH) {
            issue(c + 1, buf ^ 1);
            asm volatile("cp.async.wait_group 1;");
        } else {
            asm volatile("cp.async.wait_group 0;");
        }
        __syncthreads();

        const int bo = buf * BUFSZ;
#pragma unroll
        for (int kk = 0; kk < BK; kk += 8) {
            uint32_t a[4][4];
#pragma unroll
            for (int mf = 0; mf < 4; mf++)
                ldsm_x4(a[mf], smem_u32(As + bo + aOff[mf] + kk));

#pragma unroll
            for (int p = 0; p < 2; p++) {
                uint32_t w[4];
                ldsm_x4(w, smem_u32(Bs + bo + bOff[p] + kk));
#pragma unroll
                for (int mf = 0; mf < 4; mf++) {
                    mma_tf32(acc[mf][2 * p + 0], a[mf], w[0], w[1]);
                    mma_tf32(acc[mf][2 * p + 1], a[mf], w[2], w[3]);
                }
            }
        }
        __syncthreads();
    }

    // --- epilogue: combined bias + float2 stores ----------------------------
    float2 bb[4];
#pragma unroll
    for (int nf = 0; nf < 4; nf++) {
        int n = nBlk + warpN * 32 + nf * 8 + (lane & 3) * 2;
        bb[nf].x = g_bias_c[b * OO + n];
        bb[nf].y = g_bias_c[b * OO + n + 1];
    }

    float* C = out + (size_t)b * SS * OO;
#pragma unroll
    for (int mf = 0; mf < 4; mf++) {
        int m = mBlk + warpM * 64 + mf * 16 + (lane >> 2);
#pragma unroll
        for (int nf = 0; nf < 4; nf++) {
            int n = nBlk + warpN * 32 + nf * 8 + (lane & 3) * 2;
            float2 v0, v1;
            v0.x = acc[mf][nf][0] + bb[nf].x;
            v0.y = acc[mf][nf][1] + bb[nf].y;
            v1.x = acc[mf][nf][2] + bb[nf].x;
            v1.y = acc[mf][nf][3] + bb[nf].y;
            *(float2*)(C + (size_t)m * OO + n) = v0;
            *(float2*)(C + (size_t)(m + 8) * OO + n) = v1;
        }
    }
}

// ---------------- launch ------------------------------------------------------
extern "C" void kernel_launch(void* const* d_in, const int* in_sizes, int n_in,
                              void* d_out, int out_size) {
    const float* x      = (const float*)d_in[0];  // (32,512,768)
    const float* w_gate = (const float*)d_in[1];  // (768,8)
    const float* weight = (const float*)d_in[2];  // (8,768,768)
    const float* bias   = (const float*)d_in[3];  // (8,768)
    float* out = (float*)d_out;
    float* loss_out = out + (out_size - 1);

    const int smem_bytes = 4 * BUFSZ * 4;  // 73728 B (A/B double-buffered)
    cudaFuncSetAttribute(smoe_gemm_tf32,
                         cudaFuncAttributeMaxDynamicSharedMemorySize, smem_bytes);

    smoe_pool_kernel<<<dim3(BB, SCH, DD / 256), 256>>>(x);
    smoe_gate_kernel<<<1, BB>>>(w_gate, loss_out);
    smoe_combine_kernel<<<dim3(OO * DD / (256 * 4), BB), 256>>>(weight, bias);
    smoe_gemm_tf32<<<dim3(OO / BN, SS / BM, BB), 256, smem_bytes>>>(x, out);
}

// round 5
// speedup vs baseline: 2.6394x; 2.6394x over previous
#include <cuda_runtime.h>
#include <cstdint>

#define BB 32
#define SS 512
#define DD 768
#define OO 768
#define EE 8
#define SCH 8                      // pool s-chunks

#define BM 128
#define BN 128
#define BK 32
#define KCH (DD / BK)              // 24 k-chunks
#define LDA 36                     // padded row stride (floats)
#define BUFSZ (128 * LDA)          // floats per tile buffer

// ---------------- scratch (device globals; no allocation allowed) ----------
__device__ float g_pool_part[SCH * BB * DD];
__device__ float g_gate_val[BB * 2];
__device__ int   g_gate_idx[BB * 2];

// ---------------- kernel 1: partial pooled sums ------------------------------
__global__ void smoe_pool_kernel(const float* __restrict__ x) {
    const int b = blockIdx.x;
    const int sc = blockIdx.y;
    const int d = blockIdx.z * 256 + threadIdx.x;
    const float* xp = x + (size_t)b * SS * DD + (size_t)sc * (SS / SCH) * DD + d;
    float sum = 0.f;
#pragma unroll 8
    for (int i = 0; i < SS / SCH; i++) sum += xp[(size_t)i * DD];
    g_pool_part[(sc * BB + b) * DD + d] = sum;
}

// ---------------- kernel 2: gating + top-2 + aux loss (coalesced) ------------
__device__ __forceinline__ float cv_squared8(const float* v) {
    float m = 0.f;
#pragma unroll
    for (int e = 0; e < EE; e++) m += v[e];
    m *= (1.0f / EE);
    float var = 0.f;
#pragma unroll
    for (int e = 0; e < EE; e++) { float dv = v[e] - m; var += dv * dv; }
    var *= (1.0f / (EE - 1));
    return var / (m * m + 1e-10f);
}

__global__ void smoe_gate_kernel(const float* __restrict__ w_gate,
                                 float* __restrict__ loss_out) {
    __shared__ float s_wg[DD * EE];          // 24 KB
    __shared__ float s_logits[BB][EE];
    __shared__ float s_gates[BB][EE];

    const int tid = threadIdx.x;             // 256 threads
    const int lane = tid & 31;
    const int warp = tid >> 5;               // 8 warps; warp owns 4 batches

    for (int i = tid; i < DD * EE; i += 256) s_wg[i] = w_gate[i];
    __syncthreads();

#pragma unroll
    for (int bi = 0; bi < 4; bi++) {
        const int b = warp * 4 + bi;
        float le[EE];
#pragma unroll
        for (int e = 0; e < EE; e++) le[e] = 0.f;

        for (int d = lane; d < DD; d += 32) {      // coalesced across lanes
            float pv = 0.f;
#pragma unroll
            for (int s = 0; s < SCH; s++) pv += g_pool_part[(s * BB + b) * DD + d];
            pv *= (1.0f / SS);
#pragma unroll
            for (int e = 0; e < EE; e++) le[e] += pv * s_wg[d * EE + e];
        }
#pragma unroll
        for (int e = 0; e < EE; e++) {
#pragma unroll
            for (int off = 16; off; off >>= 1)
                le[e] += __shfl_xor_sync(0xffffffffu, le[e], off);
        }
        if (lane < EE) s_logits[b][lane] = le[lane];
    }
    __syncthreads();

    if (tid < BB) {
        const int b = tid;
        float logits[EE];
#pragma unroll
        for (int e = 0; e < EE; e++) logits[e] = s_logits[b][e];

        int i1 = 0; float v1 = logits[0];
#pragma unroll
        for (int e = 1; e < EE; e++) if (logits[e] > v1) { v1 = logits[e]; i1 = e; }
        int i2 = -1; float v2 = -1e30f;
#pragma unroll
        for (int e = 0; e < EE; e++)
            if (e != i1 && logits[e] > v2) { v2 = logits[e]; i2 = e; }

        float ex = expf(v2 - v1);
        float inv = 1.0f / (1.0f + ex);
        float gtop = inv, gsec = ex * inv;

#pragma unroll
        for (int e = 0; e < EE; e++) s_gates[b][e] = 0.f;
        s_gates[b][i1] = gtop;
        s_gates[b][i2] = gsec;

        g_gate_idx[b * 2 + 0] = i1;
        g_gate_idx[b * 2 + 1] = i2;
        g_gate_val[b * 2 + 0] = gtop;
        g_gate_val[b * 2 + 1] = gsec;
    }
    __syncthreads();

    if (tid == 0) {
        float imp[EE], ldv[EE];
#pragma unroll
        for (int e = 0; e < EE; e++) {
            float s = 0.f, c = 0.f;
            for (int bi = 0; bi < BB; bi++) {
                float g = s_gates[bi][e];
                s += g;
                if (g > 0.f) c += 1.f;
            }
            imp[e] = s; ldv[e] = c;
        }
        loss_out[0] = (cv_squared8(imp) + cv_squared8(ldv)) * 0.01f;
    }
}

// ---------------- kernel 3: TF32 mma.sync GEMM (fused expert combine) --------
__device__ __forceinline__ uint32_t smem_u32(const void* p) {
    return (uint32_t)__cvta_generic_to_shared(p);
}

__device__ __forceinline__ void ldsm_x4(uint32_t (&r)[4], uint32_t addr) {
    asm volatile("ldmatrix.sync.aligned.m8n8.x4.shared.b16 {%0,%1,%2,%3}, [%4];"
                 : "=r"(r[0]), "=r"(r[1]), "=r"(r[2]), "=r"(r[3]) : "r"(addr));
}

__device__ __forceinline__ void mma_tf32(float (&d)[4], const uint32_t (&a)[4],
                                         uint32_t b0, uint32_t b1) {
    asm volatile(
        "mma.sync.aligned.m16n8k8.row.col.f32.tf32.tf32.f32 "
        "{%0,%1,%2,%3}, {%4,%5,%6,%7}, {%8,%9}, {%0,%1,%2,%3};"
        : "+f"(d[0]), "+f"(d[1]), "+f"(d[2]), "+f"(d[3])
        : "r"(a[0]), "r"(a[1]), "r"(a[2]), "r"(a[3]), "r"(b0), "r"(b1));
}

__device__ __forceinline__ void cp_async16(uint32_t dst, const float* src) {
    asm volatile("cp.async.ca.shared.global [%0], [%1], 16;" :: "r"(dst), "l"(src));
}

__global__ __launch_bounds__(256, 2)
void smoe_gemm_tf32(const float* __restrict__ x,
                    const float* __restrict__ weight,
                    const float* __restrict__ bias,
                    float* __restrict__ out) {
    extern __shared__ float sm[];
    float* As  = sm;                 // [2][BUFSZ]
    float* B0s = sm + 2 * BUFSZ;     // [2][BUFSZ]
    float* B1s = sm + 4 * BUFSZ;     // [2][BUFSZ]

    const int b = blockIdx.z;
    const int e0 = g_gate_idx[2 * b], e1 = g_gate_idx[2 * b + 1];
    const float g0 = g_gate_val[2 * b], g1 = g_gate_val[2 * b + 1];
    const int nBlk = blockIdx.x * BN;
    const int mBlk = blockIdx.y * BM;

    const int tid = threadIdx.x;
    const int lane = tid & 31;
    const int wid = tid >> 5;
    const int warpM = wid >> 2;      // 0..1 -> 64-row slab
    const int warpN = wid & 3;       // 0..3 -> 32-col slab

    const float* gA  = x      + (size_t)b  * SS * DD + (size_t)mBlk * DD;
    const float* gW0 = weight + (size_t)e0 * OO * DD + (size_t)nBlk * DD;
    const float* gW1 = weight + (size_t)e1 * OO * DD + (size_t)nBlk * DD;

    const int aRow = (lane & 7) + ((lane >> 3) & 1) * 8;
    const int aK   = ((lane >> 4) & 1) * 4;
    int aOff[4];
#pragma unroll
    for (int mf = 0; mf < 4; mf++)
        aOff[mf] = (warpM * 64 + mf * 16 + aRow) * LDA + aK;

    const int bRow = (lane & 7) + ((lane >> 4) & 1) * 8;
    const int bK   = ((lane >> 3) & 1) * 4;
    int bOff[2];
#pragma unroll
    for (int p = 0; p < 2; p++)
        bOff[p] = (warpN * 32 + p * 16 + bRow) * LDA + bK;

    float acc[4][4][4];
#pragma unroll
    for (int i = 0; i < 4; i++)
#pragma unroll
        for (int j = 0; j < 4; j++)
#pragma unroll
            for (int k = 0; k < 4; k++) acc[i][j][k] = 0.f;

    auto issue = [&](int chunk, int buf) {
        const int kt = chunk * BK;
#pragma unroll
        for (int p = 0; p < 4; p++) {
            int c = tid + p * 256;
            int m = c >> 3;
            int k4 = (c & 7) * 4;
            int so = buf * BUFSZ + m * LDA + k4;
            size_t go = (size_t)m * DD + kt + k4;
            cp_async16(smem_u32(As  + so), gA  + go);
            cp_async16(smem_u32(B0s + so), gW0 + go);
            cp_async16(smem_u32(B1s + so), gW1 + go);
        }
        asm volatile("cp.async.commit_group;");
    };

    issue(0, 0);

#pragma unroll 1
    for (int c = 0; c < KCH; c++) {
        const int buf = c & 1;
        if (c + 1 < KCH) {
            issue(c + 1, buf ^ 1);
            asm volatile("cp.async.wait_group 1;");
        } else {
            asm volatile("cp.async.wait_group 0;");
        }
        __syncthreads();

        const int bo = buf * BUFSZ;
#pragma unroll
        for (int kk = 0; kk < BK; kk += 8) {
            uint32_t a[4][4];
#pragma unroll
            for (int mf = 0; mf < 4; mf++)
                ldsm_x4(a[mf], smem_u32(As + bo + aOff[mf] + kk));

#pragma unroll
            for (int p = 0; p < 2; p++) {
                uint32_t w0[4], w1[4];
                ldsm_x4(w0, smem_u32(B0s + bo + bOff[p] + kk));
                ldsm_x4(w1, smem_u32(B1s + bo + bOff[p] + kk));
                uint32_t bc[4];
#pragma unroll
                for (int i = 0; i < 4; i++) {
                    float v = g0 * __uint_as_float(w0[i]) + g1 * __uint_as_float(w1[i]);
                    bc[i] = __float_as_uint(v);
                }
#pragma unroll
                for (int mf = 0; mf < 4; mf++) {
                    mma_tf32(acc[mf][2 * p + 0], a[mf], bc[0], bc[1]);
                    mma_tf32(acc[mf][2 * p + 1], a[mf], bc[2], bc[3]);
                }
            }
        }
        __syncthreads();
    }

    float2 bb[4];
#pragma unroll
    for (int nf = 0; nf < 4; nf++) {
        int n = nBlk + warpN * 32 + nf * 8 + (lane & 3) * 2;
        bb[nf].x = g0 * bias[e0 * OO + n]     + g1 * bias[e1 * OO + n];
        bb[nf].y = g0 * bias[e0 * OO + n + 1] + g1 * bias[e1 * OO + n + 1];
    }

    float* C = out + (size_t)b * SS * OO;
#pragma unroll
    for (int mf = 0; mf < 4; mf++) {
        int m = mBlk + warpM * 64 + mf * 16 + (lane >> 2);
#pragma unroll
        for (int nf = 0; nf < 4; nf++) {
            int n = nBlk + warpN * 32 + nf * 8 + (lane & 3) * 2;
            float2 v0, v1;
            v0.x = acc[mf][nf][0] + bb[nf].x;
            v0.y = acc[mf][nf][1] + bb[nf].y;
            v1.x = acc[mf][nf][2] + bb[nf].x;
            v1.y = acc[mf][nf][3] + bb[nf].y;
            *(float2*)(C + (size_t)m * OO + n) = v0;
            *(float2*)(C + (size_t)(m + 8) * OO + n) = v1;
        }
    }
}

// ---------------- launch ------------------------------------------------------
extern "C" void kernel_launch(void* const* d_in, const int* in_sizes, int n_in,
                              void* d_out, int out_size) {
    const float* x      = (const float*)d_in[0];  // (32,512,768)
    const float* w_gate = (const float*)d_in[1];  // (768,8)
    const float* weight = (const float*)d_in[2];  // (8,768,768)
    const float* bias   = (const float*)d_in[3];  // (8,768)
    float* out = (float*)d_out;
    float* loss_out = out + (out_size - 1);

    const int smem_bytes = 6 * BUFSZ * 4;  // 110592 B (A/W0/W1 double-buffered)
    cudaFuncSetAttribute(smoe_gemm_tf32,
                         cudaFuncAttributeMaxDynamicSharedMemorySize, smem_bytes);

    smoe_pool_kernel<<<dim3(BB, SCH, DD / 256), 256>>>(x);
    smoe_gate_kernel<<<1, 256>>>(w_gate, loss_out);
    smoe_gemm_tf32<<<dim3(OO / BN, SS / BM, BB), 256, smem_bytes>>>(x, weight, bias, out);
}

// round 9
// speedup vs baseline: 3.2698x; 1.2388x over previous
#include <cuda_runtime.h>
#include <cstdint>

#define BB 32
#define SS 512
#define DD 768
#define OO 768
#define EE 8
#define SCH 8                      // pool s-chunks

#define BM 128
#define BN 128
#define BK 32
#define KCH (DD / BK)              // 24 k-chunks
#define LDA 36                     // padded row stride (floats)
#define BUFSZ (128 * LDA)          // floats per tile buffer

// ---------------- scratch (device globals; no allocation allowed) ----------
__device__ float g_pool_part[SCH * BB * DD];
__device__ float g_gate_val[BB * 2];
__device__ int   g_gate_idx[BB * 2];
__device__ float g_wc[(size_t)BB * OO * DD];   // 75.5MB combined expert weights
__device__ float g_bias_c[BB * OO];

// ---------------- kernel 1: partial pooled sums ------------------------------
__global__ void smoe_pool_kernel(const float* __restrict__ x) {
    const int b = blockIdx.x;
    const int sc = blockIdx.y;
    const int d = blockIdx.z * 256 + threadIdx.x;
    const float* xp = x + (size_t)b * SS * DD + (size_t)sc * (SS / SCH) * DD + d;
    float sum = 0.f;
#pragma unroll 8
    for (int i = 0; i < SS / SCH; i++) sum += xp[(size_t)i * DD];
    g_pool_part[(sc * BB + b) * DD + d] = sum;
}

// ---------------- kernel 2: gating + top-2 + aux loss (coalesced) ------------
__device__ __forceinline__ float cv_squared8(const float* v) {
    float m = 0.f;
#pragma unroll
    for (int e = 0; e < EE; e++) m += v[e];
    m *= (1.0f / EE);
    float var = 0.f;
#pragma unroll
    for (int e = 0; e < EE; e++) { float dv = v[e] - m; var += dv * dv; }
    var *= (1.0f / (EE - 1));
    return var / (m * m + 1e-10f);
}

__global__ void smoe_gate_kernel(const float* __restrict__ w_gate,
                                 float* __restrict__ loss_out) {
    __shared__ float s_wg[DD * EE];          // 24 KB
    __shared__ float s_logits[BB][EE];
    __shared__ float s_gates[BB][EE];

    const int tid = threadIdx.x;             // 256 threads
    const int lane = tid & 31;
    const int warp = tid >> 5;               // 8 warps; warp owns 4 batches

    for (int i = tid; i < DD * EE; i += 256) s_wg[i] = w_gate[i];
    __syncthreads();

#pragma unroll
    for (int bi = 0; bi < 4; bi++) {
        const int b = warp * 4 + bi;
        float le[EE];
#pragma unroll
        for (int e = 0; e < EE; e++) le[e] = 0.f;

        for (int d = lane; d < DD; d += 32) {      // coalesced across lanes
            float pv = 0.f;
#pragma unroll
            for (int s = 0; s < SCH; s++) pv += g_pool_part[(s * BB + b) * DD + d];
            pv *= (1.0f / SS);
#pragma unroll
            for (int e = 0; e < EE; e++) le[e] += pv * s_wg[d * EE + e];
        }
#pragma unroll
        for (int e = 0; e < EE; e++) {
#pragma unroll
            for (int off = 16; off; off >>= 1)
                le[e] += __shfl_xor_sync(0xffffffffu, le[e], off);
        }
        if (lane < EE) s_logits[b][lane] = le[lane];
    }
    __syncthreads();

    if (tid < BB) {
        const int b = tid;
        float logits[EE];
#pragma unroll
        for (int e = 0; e < EE; e++) logits[e] = s_logits[b][e];

        int i1 = 0; float v1 = logits[0];
#pragma unroll
        for (int e = 1; e < EE; e++) if (logits[e] > v1) { v1 = logits[e]; i1 = e; }
        int i2 = -1; float v2 = -1e30f;
#pragma unroll
        for (int e = 0; e < EE; e++)
            if (e != i1 && logits[e] > v2) { v2 = logits[e]; i2 = e; }

        float ex = expf(v2 - v1);
        float inv = 1.0f / (1.0f + ex);
        float gtop = inv, gsec = ex * inv;

#pragma unroll
        for (int e = 0; e < EE; e++) s_gates[b][e] = 0.f;
        s_gates[b][i1] = gtop;
        s_gates[b][i2] = gsec;

        g_gate_idx[b * 2 + 0] = i1;
        g_gate_idx[b * 2 + 1] = i2;
        g_gate_val[b * 2 + 0] = gtop;
        g_gate_val[b * 2 + 1] = gsec;
    }
    __syncthreads();

    if (tid == 0) {
        float imp[EE], ldv[EE];
#pragma unroll
        for (int e = 0; e < EE; e++) {
            float s = 0.f, c = 0.f;
            for (int bi = 0; bi < BB; bi++) {
                float g = s_gates[bi][e];
                s += g;
                if (g > 0.f) c += 1.f;
            }
            imp[e] = s; ldv[e] = c;
        }
        loss_out[0] = (cv_squared8(imp) + cv_squared8(ldv)) * 0.01f;
    }
}

// ---------------- kernel 2.5: combine expert weights/bias per batch ----------
// Each CTA: one batch slice. 256 thr x 16 float4 per CTA -> 36 CTAs per batch.
#define CMB_V4_PER_THREAD 16
#define CMB_V4_PER_CTA (256 * CMB_V4_PER_THREAD)            // 4096 float4
#define CMB_CTAS_PER_B ((OO * DD / 4 + CMB_V4_PER_CTA - 1) / CMB_V4_PER_CTA)  // 36

__global__ __launch_bounds__(256)
void smoe_combine_kernel(const float* __restrict__ weight,
                         const float* __restrict__ bias) {
    const int b = blockIdx.y;
    const int e0 = g_gate_idx[2 * b], e1 = g_gate_idx[2 * b + 1];
    const float g0 = g_gate_val[2 * b], g1 = g_gate_val[2 * b + 1];

    const int total = OO * DD / 4;                           // 147456 float4
    const float4* w0 = (const float4*)(weight + (size_t)e0 * OO * DD);
    const float4* w1 = (const float4*)(weight + (size_t)e1 * OO * DD);
    float4* wc = (float4*)(g_wc + (size_t)b * OO * DD);

    int base = blockIdx.x * CMB_V4_PER_CTA + threadIdx.x;
#pragma unroll
    for (int p = 0; p < CMB_V4_PER_THREAD; p += 4) {
        float4 a[4], c[4];
        int idx[4];
#pragma unroll
        for (int q = 0; q < 4; q++) {
            idx[q] = base + (p + q) * 256;
            if (idx[q] < total) { a[q] = w0[idx[q]]; c[q] = w1[idx[q]]; }
        }
#pragma unroll
        for (int q = 0; q < 4; q++) {
            if (idx[q] < total) {
                float4 r;
                r.x = g0 * a[q].x + g1 * c[q].x;
                r.y = g0 * a[q].y + g1 * c[q].y;
                r.z = g0 * a[q].z + g1 * c[q].z;
                r.w = g0 * a[q].w + g1 * c[q].w;
                wc[idx[q]] = r;
            }
        }
    }

    if (blockIdx.x == 0 && threadIdx.x < OO / 4) {
        const float4* b0 = (const float4*)(bias + (size_t)e0 * OO);
        const float4* b1 = (const float4*)(bias + (size_t)e1 * OO);
        float4 x0 = b0[threadIdx.x], x1 = b1[threadIdx.x], rb;
        rb.x = g0 * x0.x + g1 * x1.x; rb.y = g0 * x0.y + g1 * x1.y;
        rb.z = g0 * x0.z + g1 * x1.z; rb.w = g0 * x0.w + g1 * x1.w;
        ((float4*)(g_bias_c + b * OO))[threadIdx.x] = rb;
    }
}

// ---------------- kernel 3: TF32 mma.sync GEMM (2-operand, measured 119us) ---
__device__ __forceinline__ uint32_t smem_u32(const void* p) {
    return (uint32_t)__cvta_generic_to_shared(p);
}

__device__ __forceinline__ void ldsm_x4(uint32_t (&r)[4], uint32_t addr) {
    asm volatile("ldmatrix.sync.aligned.m8n8.x4.shared.b16 {%0,%1,%2,%3}, [%4];"
                 : "=r"(r[0]), "=r"(r[1]), "=r"(r[2]), "=r"(r[3]) : "r"(addr));
}

__device__ __forceinline__ void mma_tf32(float (&d)[4], const uint32_t (&a)[4],
                                         uint32_t b0, uint32_t b1) {
    asm volatile(
        "mma.sync.aligned.m16n8k8.row.col.f32.tf32.tf32.f32 "
        "{%0,%1,%2,%3}, {%4,%5,%6,%7}, {%8,%9}, {%0,%1,%2,%3};"
        : "+f"(d[0]), "+f"(d[1]), "+f"(d[2]), "+f"(d[3])
        : "r"(a[0]), "r"(a[1]), "r"(a[2]), "r"(a[3]), "r"(b0), "r"(b1));
}

__device__ __forceinline__ void cp_async16(uint32_t dst, const float* src) {
    asm volatile("cp.async.ca.shared.global [%0], [%1], 16;" :: "r"(dst), "l"(src));
}

__global__ __launch_bounds__(256, 2)
void smoe_gemm_tf32(const float* __restrict__ x,
                    float* __restrict__ out) {
    extern __shared__ float sm[];
    float* As = sm;                  // [2][BUFSZ]
    float* Bs = sm + 2 * BUFSZ;      // [2][BUFSZ]

    const int b = blockIdx.z;
    const int nBlk = blockIdx.x * BN;
    const int mBlk = blockIdx.y * BM;

    const int tid = threadIdx.x;
    const int lane = tid & 31;
    const int wid = tid >> 5;
    const int warpM = wid >> 2;      // 0..1 -> 64-row slab
    const int warpN = wid & 3;       // 0..3 -> 32-col slab

    const float* gA = x    + (size_t)b * SS * DD + (size_t)mBlk * DD;
    const float* gB = g_wc + (size_t)b * OO * DD + (size_t)nBlk * DD;

    const int aRow = (lane & 7) + ((lane >> 3) & 1) * 8;
    const int aK   = ((lane >> 4) & 1) * 4;
    int aOff[4];
#pragma unroll
    for (int mf = 0; mf < 4; mf++)
        aOff[mf] = (warpM * 64 + mf * 16 + aRow) * LDA + aK;

    const int bRow = (lane & 7) + ((lane >> 4) & 1) * 8;
    const int bK   = ((lane >> 3) & 1) * 4;
    int bOff[2];
#pragma unroll
    for (int p = 0; p < 2; p++)
        bOff[p] = (warpN * 32 + p * 16 + bRow) * LDA + bK;

    float acc[4][4][4];
#pragma unroll
    for (int i = 0; i < 4; i++)
#pragma unroll
        for (int j = 0; j < 4; j++)
#pragma unroll
            for (int k = 0; k < 4; k++) acc[i][j][k] = 0.f;

    auto issue = [&](int chunk, int buf) {
        const int kt = chunk * BK;
#pragma unroll
        for (int p = 0; p < 4; p++) {
            int c = tid + p * 256;
            int m = c >> 3;
            int k4 = (c & 7) * 4;
            int so = buf * BUFSZ + m * LDA + k4;
            size_t go = (size_t)m * DD + kt + k4;
            cp_async16(smem_u32(As + so), gA + go);
            cp_async16(smem_u32(Bs + so), gB + go);
        }
        asm volatile("cp.async.commit_group;");
    };

    issue(0, 0);

#pragma unroll 1
    for (int c = 0; c < KCH; c++) {
        const int buf = c & 1;
        if (c + 1 < KCH) {
            issue(c + 1, buf ^ 1);
            asm volatile("cp.async.wait_group 1;");
        } else {
            asm volatile("cp.async.wait_group 0;");
        }
        __syncthreads();

        const int bo = buf * BUFSZ;
#pragma unroll
        for (int kk = 0; kk < BK; kk += 8) {
            uint32_t a[4][4];
#pragma unroll
            for (int mf = 0; mf < 4; mf++)
                ldsm_x4(a[mf], smem_u32(As + bo + aOff[mf] + kk));

#pragma unroll
            for (int p = 0; p < 2; p++) {
                uint32_t w[4];
                ldsm_x4(w, smem_u32(Bs + bo + bOff[p] + kk));
#pragma unroll
                for (int mf = 0; mf < 4; mf++) {
                    mma_tf32(acc[mf][2 * p + 0], a[mf], w[0], w[1]);
                    mma_tf32(acc[mf][2 * p + 1], a[mf], w[2], w[3]);
                }
            }
        }
        __syncthreads();
    }

    float2 bb[4];
#pragma unroll
    for (int nf = 0; nf < 4; nf++) {
        int n = nBlk + warpN * 32 + nf * 8 + (lane & 3) * 2;
        bb[nf].x = g_bias_c[b * OO + n];
        bb[nf].y = g_bias_c[b * OO + n + 1];
    }

    float* C = out + (size_t)b * SS * OO;
#pragma unroll
    for (int mf = 0; mf < 4; mf++) {
        int m = mBlk + warpM * 64 + mf * 16 + (lane >> 2);
#pragma unroll
        for (int nf = 0; nf < 4; nf++) {
            int n = nBlk + warpN * 32 + nf * 8 + (lane & 3) * 2;
            float2 v0, v1;
            v0.x = acc[mf][nf][0] + bb[nf].x;
            v0.y = acc[mf][nf][1] + bb[nf].y;
            v1.x = acc[mf][nf][2] + bb[nf].x;
            v1.y = acc[mf][nf][3] + bb[nf].y;
            *(float2*)(C + (size_t)m * OO + n) = v0;
            *(float2*)(C + (size_t)(m + 8) * OO + n) = v1;
        }
    }
}

// ---------------- launch ------------------------------------------------------
extern "C" void kernel_launch(void* const* d_in, const int* in_sizes, int n_in,
                              void* d_out, int out_size) {
    const float* x      = (const float*)d_in[0];  // (32,512,768)
    const float* w_gate = (const float*)d_in[1];  // (768,8)
    const float* weight = (const float*)d_in[2];  // (8,768,768)
    const float* bias   = (const float*)d_in[3];  // (8,768)
    float* out = (float*)d_out;
    float* loss_out = out + (out_size - 1);

    const int smem_bytes = 4 * BUFSZ * 4;  // 73728 B (A/B double-buffered)
    cudaFuncSetAttribute(smoe_gemm_tf32,
                         cudaFuncAttributeMaxDynamicSharedMemorySize, smem_bytes);

    smoe_pool_kernel<<<dim3(BB, SCH, DD / 256), 256>>>(x);
    smoe_gate_kernel<<<1, 256>>>(w_gate, loss_out);
    smoe_combine_kernel<<<dim3(CMB_CTAS_PER_B, BB), 256>>>(weight, bias);
    smoe_gemm_tf32<<<dim3(OO / BN, SS / BM, BB), 256, smem_bytes>>>(x, out);
}

// round 10
// speedup vs baseline: 4.2101x; 1.2876x over previous
#include <cuda_runtime.h>
#include <cuda_fp16.h>
#include <cstdint>

#define BB 32
#define SS 512
#define DD 768
#define OO 768
#define EE 8
#define SCH 8                      // pool s-chunks

// fp16 GEMM tiling
#define BM 128
#define BN 128
#define BKH 64                     // 64 halfs = 128B rows
#define KCHH (DD / BKH)            // 12 k-chunks
#define LDAH 72                    // padded row stride (halfs) -> conflict-free ldmatrix
#define BUFSZH (128 * LDAH)        // halfs per tile buffer

// ---------------- scratch (device globals; no allocation allowed) ----------
__device__ float  g_pool_part[SCH * BB * DD];
__device__ float  g_gate_val[BB * 2];
__device__ int    g_gate_idx[BB * 2];
__device__ __half g_xh[(size_t)BB * SS * DD];   // 25.2MB fp16 copy of x
__device__ __half g_wch[(size_t)BB * OO * DD];  // 37.7MB combined expert weights (fp16)
__device__ float  g_bias_c[BB * OO];

// ---------------- kernel 1: partial pooled sums + fp16 conversion of x -------
__global__ void smoe_pool_kernel(const float* __restrict__ x) {
    const int b = blockIdx.x;
    const int sc = blockIdx.y;
    const int d = blockIdx.z * 256 + threadIdx.x;
    const size_t base = (size_t)b * SS * DD + (size_t)sc * (SS / SCH) * DD + d;
    const float* xp = x + base;
    __half* xh = g_xh + base;
    float sum = 0.f;
#pragma unroll 8
    for (int i = 0; i < SS / SCH; i++) {
        float v = xp[(size_t)i * DD];
        sum += v;
        xh[(size_t)i * DD] = __float2half_rn(v);
    }
    g_pool_part[(sc * BB + b) * DD + d] = sum;
}

// ---------------- kernel 2: gating + top-2 + aux loss (coalesced) ------------
__device__ __forceinline__ float cv_squared8(const float* v) {
    float m = 0.f;
#pragma unroll
    for (int e = 0; e < EE; e++) m += v[e];
    m *= (1.0f / EE);
    float var = 0.f;
#pragma unroll
    for (int e = 0; e < EE; e++) { float dv = v[e] - m; var += dv * dv; }
    var *= (1.0f / (EE - 1));
    return var / (m * m + 1e-10f);
}

__global__ void smoe_gate_kernel(const float* __restrict__ w_gate,
                                 float* __restrict__ loss_out) {
    __shared__ float s_wg[DD * EE];          // 24 KB
    __shared__ float s_logits[BB][EE];
    __shared__ float s_gates[BB][EE];

    const int tid = threadIdx.x;             // 256 threads
    const int lane = tid & 31;
    const int warp = tid >> 5;               // 8 warps; warp owns 4 batches

    for (int i = tid; i < DD * EE; i += 256) s_wg[i] = w_gate[i];
    __syncthreads();

#pragma unroll
    for (int bi = 0; bi < 4; bi++) {
        const int b = warp * 4 + bi;
        float le[EE];
#pragma unroll
        for (int e = 0; e < EE; e++) le[e] = 0.f;

        for (int d = lane; d < DD; d += 32) {
            float pv = 0.f;
#pragma unroll
            for (int s = 0; s < SCH; s++) pv += g_pool_part[(s * BB + b) * DD + d];
            pv *= (1.0f / SS);
#pragma unroll
            for (int e = 0; e < EE; e++) le[e] += pv * s_wg[d * EE + e];
        }
#pragma unroll
        for (int e = 0; e < EE; e++) {
#pragma unroll
            for (int off = 16; off; off >>= 1)
                le[e] += __shfl_xor_sync(0xffffffffu, le[e], off);
        }
        if (lane < EE) s_logits[b][lane] = le[lane];
    }
    __syncthreads();

    if (tid < BB) {
        const int b = tid;
        float logits[EE];
#pragma unroll
        for (int e = 0; e < EE; e++) logits[e] = s_logits[b][e];

        int i1 = 0; float v1 = logits[0];
#pragma unroll
        for (int e = 1; e < EE; e++) if (logits[e] > v1) { v1 = logits[e]; i1 = e; }
        int i2 = -1; float v2 = -1e30f;
#pragma unroll
        for (int e = 0; e < EE; e++)
            if (e != i1 && logits[e] > v2) { v2 = logits[e]; i2 = e; }

        float ex = expf(v2 - v1);
        float inv = 1.0f / (1.0f + ex);
        float gtop = inv, gsec = ex * inv;

#pragma unroll
        for (int e = 0; e < EE; e++) s_gates[b][e] = 0.f;
        s_gates[b][i1] = gtop;
        s_gates[b][i2] = gsec;

        g_gate_idx[b * 2 + 0] = i1;
        g_gate_idx[b * 2 + 1] = i2;
        g_gate_val[b * 2 + 0] = gtop;
        g_gate_val[b * 2 + 1] = gsec;
    }
    __syncthreads();

    if (tid == 0) {
        float imp[EE], ldv[EE];
#pragma unroll
        for (int e = 0; e < EE; e++) {
            float s = 0.f, c = 0.f;
            for (int bi = 0; bi < BB; bi++) {
                float g = s_gates[bi][e];
                s += g;
                if (g > 0.f) c += 1.f;
            }
            imp[e] = s; ldv[e] = c;
        }
        loss_out[0] = (cv_squared8(imp) + cv_squared8(ldv)) * 0.01f;
    }
}

// ---------------- kernel 2.5: combine expert weights/bias -> fp16 ------------
#define CMB_V4_PER_THREAD 16
#define CMB_V4_PER_CTA (256 * CMB_V4_PER_THREAD)            // 4096 float4
#define CMB_CTAS_PER_B ((OO * DD / 4 + CMB_V4_PER_CTA - 1) / CMB_V4_PER_CTA)  // 36

__global__ __launch_bounds__(256)
void smoe_combine_kernel(const float* __restrict__ weight,
                         const float* __restrict__ bias) {
    const int b = blockIdx.y;
    const int e0 = g_gate_idx[2 * b], e1 = g_gate_idx[2 * b + 1];
    const float g0 = g_gate_val[2 * b], g1 = g_gate_val[2 * b + 1];

    const int total = OO * DD / 4;                           // 147456 float4
    const float4* w0 = (const float4*)(weight + (size_t)e0 * OO * DD);
    const float4* w1 = (const float4*)(weight + (size_t)e1 * OO * DD);
    __half2* wc2 = (__half2*)(g_wch + (size_t)b * OO * DD);

    int base = blockIdx.x * CMB_V4_PER_CTA + threadIdx.x;
#pragma unroll
    for (int p = 0; p < CMB_V4_PER_THREAD; p += 4) {
        float4 a[4], c[4];
        int idx[4];
#pragma unroll
        for (int q = 0; q < 4; q++) {
            idx[q] = base + (p + q) * 256;
            if (idx[q] < total) { a[q] = w0[idx[q]]; c[q] = w1[idx[q]]; }
        }
#pragma unroll
        for (int q = 0; q < 4; q++) {
            if (idx[q] < total) {
                float rx = g0 * a[q].x + g1 * c[q].x;
                float ry = g0 * a[q].y + g1 * c[q].y;
                float rz = g0 * a[q].z + g1 * c[q].z;
                float rw = g0 * a[q].w + g1 * c[q].w;
                wc2[idx[q] * 2 + 0] = __floats2half2_rn(rx, ry);
                wc2[idx[q] * 2 + 1] = __floats2half2_rn(rz, rw);
            }
        }
    }

    if (blockIdx.x == 0 && threadIdx.x < OO / 4) {
        const float4* b0 = (const float4*)(bias + (size_t)e0 * OO);
        const float4* b1 = (const float4*)(bias + (size_t)e1 * OO);
        float4 x0 = b0[threadIdx.x], x1 = b1[threadIdx.x], rb;
        rb.x = g0 * x0.x + g1 * x1.x; rb.y = g0 * x0.y + g1 * x1.y;
        rb.z = g0 * x0.z + g1 * x1.z; rb.w = g0 * x0.w + g1 * x1.w;
        ((float4*)(g_bias_c + b * OO))[threadIdx.x] = rb;
    }
}

// ---------------- kernel 3: FP16 mma.sync GEMM (2-operand) -------------------
__device__ __forceinline__ uint32_t smem_u32(const void* p) {
    return (uint32_t)__cvta_generic_to_shared(p);
}

__device__ __forceinline__ void ldsm_x4(uint32_t (&r)[4], uint32_t addr) {
    asm volatile("ldmatrix.sync.aligned.m8n8.x4.shared.b16 {%0,%1,%2,%3}, [%4];"
                 : "=r"(r[0]), "=r"(r[1]), "=r"(r[2]), "=r"(r[3]) : "r"(addr));
}

__device__ __forceinline__ void mma_f16(float (&d)[4], const uint32_t (&a)[4],
                                        uint32_t b0, uint32_t b1) {
    asm volatile(
        "mma.sync.aligned.m16n8k16.row.col.f32.f16.f16.f32 "
        "{%0,%1,%2,%3}, {%4,%5,%6,%7}, {%8,%9}, {%0,%1,%2,%3};"
        : "+f"(d[0]), "+f"(d[1]), "+f"(d[2]), "+f"(d[3])
        : "r"(a[0]), "r"(a[1]), "r"(a[2]), "r"(a[3]), "r"(b0), "r"(b1));
}

__device__ __forceinline__ void cp_async16(uint32_t dst, const void* src) {
    asm volatile("cp.async.ca.shared.global [%0], [%1], 16;" :: "r"(dst), "l"(src));
}

__global__ __launch_bounds__(256, 2)
void smoe_gemm_f16(float* __restrict__ out) {
    extern __shared__ __half smh[];
    __half* As = smh;                   // [2][BUFSZH]
    __half* Bs = smh + 2 * BUFSZH;      // [2][BUFSZH]

    const int b = blockIdx.z;
    const int nBlk = blockIdx.x * BN;
    const int mBlk = blockIdx.y * BM;

    const int tid = threadIdx.x;
    const int lane = tid & 31;
    const int wid = tid >> 5;
    const int warpM = wid >> 2;      // 0..1 -> 64-row slab
    const int warpN = wid & 3;       // 0..3 -> 32-col slab

    const __half* gA = g_xh  + (size_t)b * SS * DD + (size_t)mBlk * DD;
    const __half* gB = g_wch + (size_t)b * OO * DD + (size_t)nBlk * DD;

    // A frag (16x16 fp16): row = lane%16, k-half (8 halfs) = lane/16
    const int aRow = (lane & 7) + ((lane >> 3) & 1) * 8;
    const int aK   = ((lane >> 4) & 1) * 8;
    int aOff[4];
#pragma unroll
    for (int mf = 0; mf < 4; mf++)
        aOff[mf] = (warpM * 64 + mf * 16 + aRow) * LDAH + aK;

    // B pair (16 n-rows x 16 k): n-half = lane/16, k-half = (lane>>3)&1
    const int bRow = (lane & 7) + ((lane >> 4) & 1) * 8;
    const int bK   = ((lane >> 3) & 1) * 8;
    int bOff[2];
#pragma unroll
    for (int p = 0; p < 2; p++)
        bOff[p] = (warpN * 32 + p * 16 + bRow) * LDAH + bK;

    float acc[4][4][4];
#pragma unroll
    for (int i = 0; i < 4; i++)
#pragma unroll
        for (int j = 0; j < 4; j++)
#pragma unroll
            for (int k = 0; k < 4; k++) acc[i][j][k] = 0.f;

    // --- cp.async tile loader: 128x64 halfs (16KB) per stream ---------------
    auto issue = [&](int chunk, int buf) {
        const int kt = chunk * BKH;
#pragma unroll
        for (int p = 0; p < 4; p++) {
            int c = tid + p * 256;        // 0..1023 16B units
            int row = c >> 3;
            int q8 = (c & 7) * 8;         // half offset within row
            int so = buf * BUFSZH + row * LDAH + q8;
            size_t go = (size_t)row * DD + kt + q8;
            cp_async16(smem_u32(As + so), gA + go);
            cp_async16(smem_u32(Bs + so), gB + go);
        }
        asm volatile("cp.async.commit_group;");
    };

    issue(0, 0);

#pragma unroll 1
    for (int c = 0; c < KCHH; c++) {
        const int buf = c & 1;
        if (c + 1 < KCHH) {
            issue(c + 1, buf ^ 1);
            asm volatile("cp.async.wait_group 1;");
        } else {
            asm volatile("cp.async.wait_group 0;");
        }
        __syncthreads();

        const int bo = buf * BUFSZH;
#pragma unroll
        for (int kk = 0; kk < BKH; kk += 16) {
            uint32_t a[4][4];
#pragma unroll
            for (int mf = 0; mf < 4; mf++)
                ldsm_x4(a[mf], smem_u32(As + bo + aOff[mf] + kk));

#pragma unroll
            for (int p = 0; p < 2; p++) {
                uint32_t w[4];
                ldsm_x4(w, smem_u32(Bs + bo + bOff[p] + kk));
#pragma unroll
                for (int mf = 0; mf < 4; mf++) {
                    mma_f16(acc[mf][2 * p + 0], a[mf], w[0], w[1]);
                    mma_f16(acc[mf][2 * p + 1], a[mf], w[2], w[3]);
                }
            }
        }
        __syncthreads();
    }

    // --- epilogue: combined bias + float2 stores ----------------------------
    float2 bb[4];
#pragma unroll
    for (int nf = 0; nf < 4; nf++) {
        int n = nBlk + warpN * 32 + nf * 8 + (lane & 3) * 2;
        bb[nf].x = g_bias_c[b * OO + n];
        bb[nf].y = g_bias_c[b * OO + n + 1];
    }

    float* C = out + (size_t)b * SS * OO;
#pragma unroll
    for (int mf = 0; mf < 4; mf++) {
        int m = mBlk + warpM * 64 + mf * 16 + (lane >> 2);
#pragma unroll
        for (int nf = 0; nf < 4; nf++) {
            int n = nBlk + warpN * 32 + nf * 8 + (lane & 3) * 2;
            float2 v0, v1;
            v0.x = acc[mf][nf][0] + bb[nf].x;
            v0.y = acc[mf][nf][1] + bb[nf].y;
            v1.x = acc[mf][nf][2] + bb[nf].x;
            v1.y = acc[mf][nf][3] + bb[nf].y;
            *(float2*)(C + (size_t)m * OO + n) = v0;
            *(float2*)(C + (size_t)(m + 8) * OO + n) = v1;
        }
    }
}

// ---------------- launch ------------------------------------------------------
extern "C" void kernel_launch(void* const* d_in, const int* in_sizes, int n_in,
                              void* d_out, int out_size) {
    const float* x      = (const float*)d_in[0];  // (32,512,768)
    const float* w_gate = (const float*)d_in[1];  // (768,8)
    const float* weight = (const float*)d_in[2];  // (8,768,768)
    const float* bias   = (const float*)d_in[3];  // (8,768)
    float* out = (float*)d_out;
    float* loss_out = out + (out_size - 1);

    const int smem_bytes = 4 * BUFSZH * 2;  // 73728 B (A/B double-buffered, fp16)
    cudaFuncSetAttribute(smoe_gemm_f16,
                         cudaFuncAttributeMaxDynamicSharedMemorySize, smem_bytes);

    smoe_pool_kernel<<<dim3(BB, SCH, DD / 256), 256>>>(x);
    smoe_gate_kernel<<<1, 256>>>(w_gate, loss_out);
    smoe_combine_kernel<<<dim3(CMB_CTAS_PER_B, BB), 256>>>(weight, bias);
    smoe_gemm_f16<<<dim3(OO / BN, SS / BM, BB), 256, smem_bytes>>>(out);
}